// round 7
// baseline (speedup 1.0000x reference)
#include <cuda_runtime.h>
#include <cstdint>
#include <math.h>

#define T_STEPS 1024
#define BATCH   16
#define DIM     1024
#define BD      (BATCH*DIM)           /* 16384 */
#define TBD     (T_STEPS*BATCH*DIM)   /* 16777216 */
#define NCTA    128
#define NTHR    256
#define EPSF    1e-8f
#define MAXR    0.999f

// ---------------- device scratch (no allocations allowed) -------------------
__device__ float    g_G[TBD];          // x @ W_x^T + b
__device__ float    g_hbuf[2][BD];     // double-buffered hidden state [b][d]
__device__ float    g_u[DIM];
__device__ float    g_v[DIM];
__device__ float    g_vraw[DIM];
__device__ float    g_uraw[DIM];
__device__ unsigned g_flag[NCTA];
__device__ unsigned g_gen;

// ---------------- low-level helpers ----------------------------------------
__device__ __forceinline__ unsigned ld_acq(const unsigned* p) {
    unsigned v;
    asm volatile("ld.acquire.gpu.u32 %0, [%1];" : "=r"(v) : "l"(p) : "memory");
    return v;
}
__device__ __forceinline__ void st_rel(unsigned* p, unsigned v) {
    asm volatile("st.release.gpu.u32 [%0], %1;" :: "l"(p), "r"(v) : "memory");
}
__device__ __forceinline__ unsigned long long pack2(float a, float b) {
    unsigned long long r;
    asm("mov.b64 %0, {%1, %2};" : "=l"(r) : "f"(a), "f"(b));
    return r;
}
__device__ __forceinline__ void fma2(unsigned long long& d,
                                     unsigned long long a, unsigned long long b) {
    asm("fma.rn.f32x2 %0, %1, %2, %0;" : "+l"(d) : "l"(a), "l"(b));
}
__device__ __forceinline__ float fold2(unsigned long long v) {
    float lo, hi;
    asm("mov.b64 {%0, %1}, %2;" : "=f"(lo), "=f"(hi) : "l"(v));
    return lo + hi;
}
__device__ __forceinline__ void unpack2(unsigned long long v, float& lo, float& hi) {
    asm("mov.b64 {%0, %1}, %2;" : "=f"(lo), "=f"(hi) : "l"(v));
}
__device__ __forceinline__ void cp_async16(void* dst, const void* src) {
    unsigned s = (unsigned)__cvta_generic_to_shared(dst);
    asm volatile("cp.async.cg.shared.global [%0], [%1], 16;" :: "r"(s), "l"(src));
}
__device__ __forceinline__ void mbar_init(unsigned a, unsigned cnt) {
    asm volatile("mbarrier.init.shared.b64 [%0], %1;" :: "r"(a), "r"(cnt) : "memory");
}
__device__ __forceinline__ void mbar_wait(unsigned a, unsigned par) {
    unsigned done;
    do {
        asm volatile(
            "{\n\t.reg .pred p;\n\t"
            "mbarrier.try_wait.parity.acquire.cta.shared::cta.b64 p, [%1], %2;\n\t"
            "selp.b32 %0, 1, 0, p;\n\t}"
            : "=r"(done) : "r"(a), "r"(par) : "memory");
    } while (!done);
}
// .noinc: arrival counts against the init count (default form self-increments
// the pending count and would deadlock a fixed-count barrier).
__device__ __forceinline__ void cp_async_arrive_noinc(unsigned mbar) {
    asm volatile("cp.async.mbarrier.arrive.noinc.shared.b64 [%0];" :: "r"(mbar) : "memory");
}

// fast, overflow-safe tanh via ex2-based expf (~1e-7 rel acc)
__device__ __forceinline__ float fast_tanh(float s) {
    float e = __expf(2.f * fabsf(s));
    float r = 1.f - 2.f / (e + 1.f);
    return copysignf(r, s);
}

// Global grid barrier (phase A only). CTA0 polls all flags, publishes g_gen.
__device__ __forceinline__ void global_barrier(int c, unsigned target) {
    __syncthreads();
    if (threadIdx.x < 32) {
        if (threadIdx.x == 0) {
            __threadfence();
            st_rel(&g_flag[c], target);
        }
        if (c == 0) {
            unsigned ok;
            do {
                ok = 1u;
#pragma unroll
                for (int q = 0; q < 4; ++q)
                    ok &= (unsigned)(ld_acq(&g_flag[threadIdx.x + 32*q]) >= target);
            } while (!__all_sync(0xffffffffu, ok));
            if (threadIdx.x == 0) st_rel(&g_gen, target);
        } else if (threadIdx.x == 0) {
            while (ld_acq(&g_gen) < target) { }
        }
    }
    __syncthreads();
}

// ---------------- GEMM (f32x2, sw-pipelined): g_G = X @ Wx^T + bias ---------
__global__ void __launch_bounds__(256) gemm_kernel(
    const float* __restrict__ X, const float* __restrict__ Wx,
    const float* __restrict__ bias)
{
    __shared__ float As[8][128];
    __shared__ float Bs[8][128];
    const int tid  = threadIdx.x;
    const int bn0  = blockIdx.x * 128;
    const int bm0  = blockIdx.y * 128;
    const int tm   = tid & 15;
    const int tn   = tid >> 4;
    const int lrow = tid >> 1;
    const int lk   = (tid & 1) * 4;
    const float* Ap = X  + (size_t)(bm0 + lrow) * DIM + lk;
    const float* Bp = Wx + (size_t)(bn0 + lrow) * DIM + lk;

    unsigned long long acc2[8][4];
#pragma unroll
    for (int i = 0; i < 8; ++i)
#pragma unroll
        for (int q = 0; q < 4; ++q) acc2[i][q] = 0ull;

    float4 av = *(const float4*)(Ap);
    float4 bv = *(const float4*)(Bp);

    for (int k0 = 0; k0 < DIM; k0 += 8) {
        __syncthreads();
        As[lk+0][lrow] = av.x; As[lk+1][lrow] = av.y;
        As[lk+2][lrow] = av.z; As[lk+3][lrow] = av.w;
        Bs[lk+0][lrow] = bv.x; Bs[lk+1][lrow] = bv.y;
        Bs[lk+2][lrow] = bv.z; Bs[lk+3][lrow] = bv.w;
        __syncthreads();
        float4 av2, bv2;
        if (k0 + 8 < DIM) {
            av2 = *(const float4*)(Ap + k0 + 8);
            bv2 = *(const float4*)(Bp + k0 + 8);
        }
#pragma unroll
        for (int kk = 0; kk < 8; ++kk) {
            float af[8], bf[8];
#pragma unroll
            for (int i = 0; i < 4; ++i) {
                af[i]   = As[kk][tm*4 + i];
                af[4+i] = As[kk][64 + tm*4 + i];
                bf[i]   = Bs[kk][tn*4 + i];
                bf[4+i] = Bs[kk][64 + tn*4 + i];
            }
            unsigned long long bp[4], ap[8];
#pragma unroll
            for (int q = 0; q < 4; ++q) bp[q] = pack2(bf[2*q], bf[2*q+1]);
#pragma unroll
            for (int i = 0; i < 8; ++i) ap[i] = pack2(af[i], af[i]);
#pragma unroll
            for (int i = 0; i < 8; ++i)
#pragma unroll
                for (int q = 0; q < 4; ++q) fma2(acc2[i][q], ap[i], bp[q]);
        }
        av = av2; bv = bv2;
    }
    float bf2[8];
#pragma unroll
    for (int i = 0; i < 4; ++i) {
        bf2[i]   = bias[bn0 + tn*4 + i];
        bf2[4+i] = bias[bn0 + 64 + tn*4 + i];
    }
#pragma unroll
    for (int i = 0; i < 8; ++i) {
        int m = bm0 + ((i < 4) ? (tm*4 + i) : (64 + tm*4 + (i - 4)));
        float a0,a1,a2,a3,a4,a5,a6,a7;
        unpack2(acc2[i][0], a0, a1);
        unpack2(acc2[i][1], a2, a3);
        unpack2(acc2[i][2], a4, a5);
        unpack2(acc2[i][3], a6, a7);
        float4 o0, o1;
        o0.x = a0 + bf2[0]; o0.y = a1 + bf2[1];
        o0.z = a2 + bf2[2]; o0.w = a3 + bf2[3];
        o1.x = a4 + bf2[4]; o1.y = a5 + bf2[5];
        o1.z = a6 + bf2[6]; o1.w = a7 + bf2[7];
        *(float4*)&g_G[(size_t)m * DIM + bn0 + tn*4]      = o0;
        *(float4*)&g_G[(size_t)m * DIM + bn0 + 64 + tn*4] = o1;
    }
}

// ---------------- persistent: power iter + recurrence + gating --------------
__global__ void __launch_bounds__(NTHR, 1) rnn_kernel(
    const float* __restrict__ z,   const float* __restrict__ h0,
    const float* __restrict__ Wh,  const float* __restrict__ logr,
    const float* __restrict__ u0,  float* __restrict__ out)
{
    __shared__ __align__(128) float h_sm[4*DIM];  // 16 KB [bi][k]
    __shared__ float red[8*16*36];                // warp reduction scratch
    __shared__ float nrm[NTHR];
    __shared__ __align__(8) unsigned long long mbar[8];   // one per j-block

    const int c    = blockIdx.x;
    const int g    = c >> 5;                      // batch group (4 batches)
    const int dg   = c & 31;                      // dim group (32 dims)
    const int tid  = threadIdx.x;
    const int lane = tid & 31;
    const int w    = tid >> 5;                    // 8 warps = 8 x (4 dims)

    float* outs  = out;
    float* h_all = out + TBD;

    const unsigned hsm0  = (unsigned)__cvta_generic_to_shared(h_sm);
    const unsigned hbase = hsm0 + 16*lane;
    const unsigned mb0   = (unsigned)__cvta_generic_to_shared(mbar);

    unsigned bt = ld_acq(&g_flag[c]);             // monotonic base across replays

    // ---- (a) init ----
    if (tid < 8) mbar_init(mb0 + 8*tid, 32);      // 32 .noinc arrivals per phase
    if (tid < 128) {
        int i = c*128 + tid;
        float v = h0[i];
        g_hbuf[0][i] = v;
        h_all[i]     = v;
    }
    if (tid < 8) g_u[c*8 + tid] = u0[c*8 + tid];
    global_barrier(c, ++bt);

    // ---- (b) 3-step power iteration (CTA owns 8 rows/cols: 8c..8c+8) ----
    float sigma = 0.f;
    for (int it = 0; it < 3; ++it) {
        {   // vraw = Wh^T u
            int jj = tid & 7, rc = tid >> 3;
            const float* col = Wh + 8*c + jj;
            float p = 0.f;
            for (int ii = 0; ii < 32; ++ii) {
                int i = rc*32 + ii;
                p += __ldg(col + (size_t)i*DIM) * __ldcg(&g_u[i]);
            }
            nrm[tid] = p;
        }
        __syncthreads();
        if (tid < 8) {
            float s = 0.f;
            for (int rc = 0; rc < 32; ++rc) s += nrm[tid + 8*rc];
            g_vraw[8*c + tid] = s;
        }
        global_barrier(c, ++bt);
        {   // normalize v (redundantly per CTA, deterministic)
            float p = 0.f;
            for (int i = tid; i < DIM; i += NTHR) { float x = __ldcg(&g_vraw[i]); p += x*x; }
            nrm[tid] = p; __syncthreads();
            for (int o = 128; o > 0; o >>= 1) {
                if (tid < o) nrm[tid] += nrm[tid + o];
                __syncthreads();
            }
            float inv = 1.f / (sqrtf(nrm[0]) + EPSF);
            __syncthreads();
            if (tid < 8) g_v[8*c + tid] = __ldcg(&g_vraw[8*c + tid]) * inv;
        }
        global_barrier(c, ++bt);
        {   // uraw = Wh v  (warp per row)
            int r = 8*c + w;
            const float* row = Wh + (size_t)r*DIM;
            float p = 0.f;
            for (int j = 0; j < 32; ++j) {
                int k = lane + 32*j;
                p += __ldg(row + k) * __ldcg(&g_v[k]);
            }
#pragma unroll
            for (int o = 16; o; o >>= 1) p += __shfl_xor_sync(0xffffffffu, p, o);
            if (lane == 0) g_uraw[r] = p;
        }
        global_barrier(c, ++bt);
        {   // normalize u / sigma
            float p = 0.f;
            for (int i = tid; i < DIM; i += NTHR) { float x = __ldcg(&g_uraw[i]); p += x*x; }
            nrm[tid] = p; __syncthreads();
            for (int o = 128; o > 0; o >>= 1) {
                if (tid < o) nrm[tid] += nrm[tid + o];
                __syncthreads();
            }
            float s2 = nrm[0];
            __syncthreads();
            if (it < 2) {
                float inv = 1.f / (sqrtf(s2) + EPSF);
                if (tid < 8) g_u[8*c + tid] = __ldcg(&g_uraw[8*c + tid]) * inv;
                global_barrier(c, ++bt);
            } else {
                sigma = s2 / (sqrtf(s2) + EPSF);   // |u . Wh v|
            }
        }
    }
    // all flags now equal bt for every CTA

    // ---- (c) W_eff slice into registers, pre-packed as f32x2 pairs ----
    unsigned long long w01[4][8], w23[4][8];
#pragma unroll
    for (int oi = 0; oi < 4; ++oi) {
        int d = dg*32 + 4*w + oi;
        float lr   = __ldg(&logr[d]);
        float rad  = MAXR / (1.f + expf(-lr));
        float mult = rad / (sigma + EPSF);
        const float* row = Wh + (size_t)d*DIM + 4*lane;
#pragma unroll
        for (int j = 0; j < 8; ++j) {
            float4 wv = *(const float4*)(row + 128*j);
            w01[oi][j] = pack2(wv.x*mult, wv.y*mult);
            w23[oi][j] = pack2(wv.z*mult, wv.w*mult);
        }
    }

    // epilogue mapping (lanes 0..15): bi = lane>>2, oi = lane&3
    const int eb   = 4*g + (lane >> 2);
    const int ed   = dg*32 + 4*w + (lane & 3);
    const int eidx = eb*DIM + ed;
    float* myred = red + w*576;
    const unsigned* myflags = &g_flag[g*32];

    // ---- (d) recurrence : producer-ordered dataflow -----------------------
    const float* hsrc[2] = { &g_hbuf[0][4*g*DIM], &g_hbuf[1][4*g*DIM] };
    for (int t = 0; t < T_STEPS; ++t) {
        // prefetch G and z early (independent of h)
        float gpre = 0.f, zpre = 0.f;
        size_t gi = (size_t)t*BD + eidx;
        if (lane < 16) {
            gpre = __ldg(&g_G[gi]);
            zpre = __ldg(&z[gi]);
        }

        // warp 0 stages h in producer order; j-block j needs producers 4j..4j+3
        if (w == 0) {
            const float* src = hsrc[t & 1];
            unsigned tgt = bt + (unsigned)t;
            for (int j = 0; j < 8; ++j) {
                unsigned ok;
                do { ok = (lane < 4) ? (unsigned)(ld_acq(&myflags[4*j + lane]) >= tgt) : 1u; }
                while (!__all_sync(0xffffffffu, ok));
#pragma unroll
                for (int r = 0; r < 4; ++r) {
                    int idx = r*32 + lane;        // 0..127 : 16B segments
                    int bi  = idx >> 5;
                    int o16 = idx & 31;
                    int off = bi*1024 + j*128 + o16*4;
                    cp_async16(&h_sm[off], src + off);
                }
                cp_async_arrive_noinc(mb0 + 8*j); // arrives when these land
            }
        }

        unsigned long long acc[4][4];
#pragma unroll
        for (int bi = 0; bi < 4; ++bi)
#pragma unroll
            for (int oi = 0; oi < 4; ++oi) acc[bi][oi] = 0ull;

#pragma unroll
        for (int j = 0; j < 8; ++j) {
            mbar_wait(mb0 + 8*j, t & 1);
#pragma unroll
            for (int bi = 0; bi < 4; ++bi) {
                unsigned long long h01, h23;
                asm volatile("ld.shared.v2.b64 {%0, %1}, [%2];"
                             : "=l"(h01), "=l"(h23)
                             : "r"(hbase + bi*4096 + j*512));
#pragma unroll
                for (int oi = 0; oi < 4; ++oi) {
                    fma2(acc[bi][oi], w01[oi][j], h01);
                    fma2(acc[bi][oi], w23[oi][j], h23);
                }
            }
        }

        // fold f32x2 halves, reduce k across 32 lanes via padded smem
#pragma unroll
        for (int bi = 0; bi < 4; ++bi)
#pragma unroll
            for (int oi = 0; oi < 4; ++oi)
                myred[(bi*4 + oi)*36 + lane] = fold2(acc[bi][oi]);
        __syncwarp();

        float hn = 0.f;
        if (lane < 16) {
            const float* rr = myred + lane*36;
            float4 s4 = make_float4(0.f, 0.f, 0.f, 0.f);
#pragma unroll
            for (int q = 0; q < 8; ++q) {
                float4 v = *(const float4*)(rr + q*4);
                s4.x += v.x; s4.y += v.y; s4.z += v.z; s4.w += v.w;
            }
            float s = (s4.x + s4.y) + (s4.z + s4.w);
            hn = fast_tanh(s + gpre);
            // CRITICAL-PATH store: next-step hidden state
            __stcg(&g_hbuf[(t + 1) & 1][eidx], hn);
        }
        __syncthreads();                          // all h stores issued

        // ARRIVE: publish (fence drains only the tiny h stores)
        if (tid == 0) {
            __threadfence();
            st_rel(&g_flag[c], bt + (unsigned)t + 1u);
        }

        // off-critical-path stores: gated output + h_all
        if (lane < 16) {
            float ov = hn * (zpre / (1.f + __expf(-zpre)));   // h * silu(z)
            outs[gi]       = ov;
            h_all[gi + BD] = hn;
        }
    }
}

// ---------------- launch -----------------------------------------------------
extern "C" void kernel_launch(void* const* d_in, const int* in_sizes, int n_in,
                              void* d_out, int out_size) {
    const float* x    = (const float*)d_in[0];
    const float* z    = (const float*)d_in[1];
    const float* h0   = (const float*)d_in[2];
    const float* Wx   = (const float*)d_in[3];
    const float* Wh   = (const float*)d_in[4];
    const float* logr = (const float*)d_in[5];
    const float* b    = (const float*)d_in[6];
    const float* u0   = (const float*)d_in[7];
    float* out = (float*)d_out;

    gemm_kernel<<<dim3(DIM/128, (T_STEPS*BATCH)/128), 256>>>(x, Wx, b);
    rnn_kernel<<<NCTA, NTHR>>>(z, h0, Wh, logr, u0, out);
}

// round 14
// speedup vs baseline: 1.7881x; 1.7881x over previous
#include <cuda_runtime.h>
#include <cstdint>
#include <math.h>

#define T_STEPS 1024
#define BATCH   16
#define DIM     1024
#define BD      (BATCH*DIM)           /* 16384 */
#define TBD     (T_STEPS*BATCH*DIM)   /* 16777216 */
#define NCTA    128
#define NTHR    256
#define EPSF    1e-8f
#define MAXR    0.999f

// ---------------- device scratch (no allocations allowed) -------------------
__device__ float    g_G[TBD];          // x @ W_x^T + b
__device__ float    g_hbuf[2][BD];     // double-buffered hidden state [b][d]
__device__ float    g_u[DIM];
__device__ float    g_v[DIM];
__device__ float    g_vraw[DIM];
__device__ float    g_uraw[DIM];
__device__ unsigned g_flag[NCTA];      // phase A/B barrier flags
__device__ unsigned g_cnt[NCTA];       // per-CTA warp-arrival counters (recurrence)
__device__ unsigned g_gen;

// ---------------- low-level helpers ----------------------------------------
__device__ __forceinline__ unsigned ld_acq(const unsigned* p) {
    unsigned v;
    asm volatile("ld.acquire.gpu.u32 %0, [%1];" : "=r"(v) : "l"(p) : "memory");
    return v;
}
__device__ __forceinline__ void st_rel(unsigned* p, unsigned v) {
    asm volatile("st.release.gpu.u32 [%0], %1;" :: "l"(p), "r"(v) : "memory");
}
__device__ __forceinline__ void red_rel_add1(unsigned* p) {
    asm volatile("red.release.gpu.global.add.u32 [%0], %1;" :: "l"(p), "r"(1u) : "memory");
}
__device__ __forceinline__ unsigned long long pack2(float a, float b) {
    unsigned long long r;
    asm("mov.b64 %0, {%1, %2};" : "=l"(r) : "f"(a), "f"(b));
    return r;
}
__device__ __forceinline__ void fma2(unsigned long long& d,
                                     unsigned long long a, unsigned long long b) {
    asm("fma.rn.f32x2 %0, %1, %2, %0;" : "+l"(d) : "l"(a), "l"(b));
}
__device__ __forceinline__ float fold2(unsigned long long v) {
    float lo, hi;
    asm("mov.b64 {%0, %1}, %2;" : "=f"(lo), "=f"(hi) : "l"(v));
    return lo + hi;
}
__device__ __forceinline__ void unpack2(unsigned long long v, float& lo, float& hi) {
    asm("mov.b64 {%0, %1}, %2;" : "=f"(lo), "=f"(hi) : "l"(v));
}
__device__ __forceinline__ void cp_async16(void* dst, const void* src) {
    unsigned s = (unsigned)__cvta_generic_to_shared(dst);
    asm volatile("cp.async.cg.shared.global [%0], [%1], 16;" :: "r"(s), "l"(src));
}
__device__ __forceinline__ void cp_commit() { asm volatile("cp.async.commit_group;"); }
__device__ __forceinline__ void cp_wait1()  { asm volatile("cp.async.wait_group 1;"); }
__device__ __forceinline__ void cp_wait0()  { asm volatile("cp.async.wait_group 0;"); }

// fast, overflow-safe tanh via ex2-based expf (~1e-7 rel acc)
__device__ __forceinline__ float fast_tanh(float s) {
    float e = __expf(2.f * fabsf(s));
    float r = 1.f - 2.f / (e + 1.f);
    return copysignf(r, s);
}

// Global grid barrier (phases A/B only). CTA0 polls all flags, publishes g_gen.
__device__ __forceinline__ void global_barrier(int c, unsigned target) {
    __syncthreads();
    if (threadIdx.x < 32) {
        if (threadIdx.x == 0) {
            __threadfence();
            st_rel(&g_flag[c], target);
        }
        if (c == 0) {
            unsigned ok;
            do {
                ok = 1u;
#pragma unroll
                for (int q = 0; q < 4; ++q)
                    ok &= (unsigned)(ld_acq(&g_flag[threadIdx.x + 32*q]) >= target);
            } while (!__all_sync(0xffffffffu, ok));
            if (threadIdx.x == 0) st_rel(&g_gen, target);
        } else if (threadIdx.x == 0) {
            while (ld_acq(&g_gen) < target) { }
        }
    }
    __syncthreads();
}

// ---------------- GEMM (f32x2, sw-pipelined): g_G = X @ Wx^T + bias ---------
__global__ void __launch_bounds__(256) gemm_kernel(
    const float* __restrict__ X, const float* __restrict__ Wx,
    const float* __restrict__ bias)
{
    __shared__ float As[8][128];
    __shared__ float Bs[8][128];
    const int tid  = threadIdx.x;
    const int bn0  = blockIdx.x * 128;
    const int bm0  = blockIdx.y * 128;
    const int tm   = tid & 15;
    const int tn   = tid >> 4;
    const int lrow = tid >> 1;
    const int lk   = (tid & 1) * 4;
    const float* Ap = X  + (size_t)(bm0 + lrow) * DIM + lk;
    const float* Bp = Wx + (size_t)(bn0 + lrow) * DIM + lk;

    unsigned long long acc2[8][4];
#pragma unroll
    for (int i = 0; i < 8; ++i)
#pragma unroll
        for (int q = 0; q < 4; ++q) acc2[i][q] = 0ull;

    float4 av = *(const float4*)(Ap);
    float4 bv = *(const float4*)(Bp);

    for (int k0 = 0; k0 < DIM; k0 += 8) {
        __syncthreads();
        As[lk+0][lrow] = av.x; As[lk+1][lrow] = av.y;
        As[lk+2][lrow] = av.z; As[lk+3][lrow] = av.w;
        Bs[lk+0][lrow] = bv.x; Bs[lk+1][lrow] = bv.y;
        Bs[lk+2][lrow] = bv.z; Bs[lk+3][lrow] = bv.w;
        __syncthreads();
        float4 av2, bv2;
        if (k0 + 8 < DIM) {
            av2 = *(const float4*)(Ap + k0 + 8);
            bv2 = *(const float4*)(Bp + k0 + 8);
        }
#pragma unroll
        for (int kk = 0; kk < 8; ++kk) {
            float af[8], bf[8];
#pragma unroll
            for (int i = 0; i < 4; ++i) {
                af[i]   = As[kk][tm*4 + i];
                af[4+i] = As[kk][64 + tm*4 + i];
                bf[i]   = Bs[kk][tn*4 + i];
                bf[4+i] = Bs[kk][64 + tn*4 + i];
            }
            unsigned long long bp[4], ap[8];
#pragma unroll
            for (int q = 0; q < 4; ++q) bp[q] = pack2(bf[2*q], bf[2*q+1]);
#pragma unroll
            for (int i = 0; i < 8; ++i) ap[i] = pack2(af[i], af[i]);
#pragma unroll
            for (int i = 0; i < 8; ++i)
#pragma unroll
                for (int q = 0; q < 4; ++q) fma2(acc2[i][q], ap[i], bp[q]);
        }
        av = av2; bv = bv2;
    }
    float bf2[8];
#pragma unroll
    for (int i = 0; i < 4; ++i) {
        bf2[i]   = bias[bn0 + tn*4 + i];
        bf2[4+i] = bias[bn0 + 64 + tn*4 + i];
    }
#pragma unroll
    for (int i = 0; i < 8; ++i) {
        int m = bm0 + ((i < 4) ? (tm*4 + i) : (64 + tm*4 + (i - 4)));
        float a0,a1,a2,a3,a4,a5,a6,a7;
        unpack2(acc2[i][0], a0, a1);
        unpack2(acc2[i][1], a2, a3);
        unpack2(acc2[i][2], a4, a5);
        unpack2(acc2[i][3], a6, a7);
        float4 o0, o1;
        o0.x = a0 + bf2[0]; o0.y = a1 + bf2[1];
        o0.z = a2 + bf2[2]; o0.w = a3 + bf2[3];
        o1.x = a4 + bf2[4]; o1.y = a5 + bf2[5];
        o1.z = a6 + bf2[6]; o1.w = a7 + bf2[7];
        *(float4*)&g_G[(size_t)m * DIM + bn0 + tn*4]      = o0;
        *(float4*)&g_G[(size_t)m * DIM + bn0 + 64 + tn*4] = o1;
    }
}

// ---------------- persistent: power iter + recurrence + gating --------------
__global__ void __launch_bounds__(NTHR, 1) rnn_kernel(
    const float* __restrict__ z,   const float* __restrict__ h0,
    const float* __restrict__ Wh,  const float* __restrict__ logr,
    const float* __restrict__ u0,  float* __restrict__ out)
{
    __shared__ __align__(128) float h_sm[4*DIM];  // 16 KB [bi][k]
    __shared__ float red[8*16*36];                // warp reduction scratch
    __shared__ float nrm[NTHR];

    const int c    = blockIdx.x;
    const int g    = c >> 5;                      // batch group (4 batches)
    const int dg   = c & 31;                      // dim group (32 dims)
    const int tid  = threadIdx.x;
    const int lane = tid & 31;
    const int w    = tid >> 5;                    // 8 warps = 8 x (4 dims)

    float* outs  = out;
    float* h_all = out + TBD;

    const unsigned hsm0  = (unsigned)__cvta_generic_to_shared(h_sm);
    const unsigned hbase = hsm0 + 16*lane;

    unsigned bt  = ld_acq(&g_flag[c]);   // phase A/B barrier base (monotonic)
    unsigned bt2 = ld_acq(&g_cnt[c]);    // warp-arrival counter base (monotonic)

    // ---- (a) init ----
    if (tid < 128) {
        int i = c*128 + tid;
        float v = h0[i];
        g_hbuf[0][i] = v;
        h_all[i]     = v;
    }
    if (tid < 8) g_u[c*8 + tid] = u0[c*8 + tid];
    global_barrier(c, ++bt);

    // ---- (b) 3-step power iteration (CTA owns 8 rows/cols: 8c..8c+8) ----
    float sigma = 0.f;
    for (int it = 0; it < 3; ++it) {
        {   // vraw = Wh^T u
            int jj = tid & 7, rc = tid >> 3;
            const float* col = Wh + 8*c + jj;
            float p = 0.f;
            for (int ii = 0; ii < 32; ++ii) {
                int i = rc*32 + ii;
                p += __ldg(col + (size_t)i*DIM) * __ldcg(&g_u[i]);
            }
            nrm[tid] = p;
        }
        __syncthreads();
        if (tid < 8) {
            float s = 0.f;
            for (int rc = 0; rc < 32; ++rc) s += nrm[tid + 8*rc];
            g_vraw[8*c + tid] = s;
        }
        global_barrier(c, ++bt);
        {   // normalize v (redundantly per CTA, deterministic)
            float p = 0.f;
            for (int i = tid; i < DIM; i += NTHR) { float x = __ldcg(&g_vraw[i]); p += x*x; }
            nrm[tid] = p; __syncthreads();
            for (int o = 128; o > 0; o >>= 1) {
                if (tid < o) nrm[tid] += nrm[tid + o];
                __syncthreads();
            }
            float inv = 1.f / (sqrtf(nrm[0]) + EPSF);
            __syncthreads();
            if (tid < 8) g_v[8*c + tid] = __ldcg(&g_vraw[8*c + tid]) * inv;
        }
        global_barrier(c, ++bt);
        {   // uraw = Wh v  (warp per row)
            int r = 8*c + w;
            const float* row = Wh + (size_t)r*DIM;
            float p = 0.f;
            for (int j = 0; j < 32; ++j) {
                int k = lane + 32*j;
                p += __ldg(row + k) * __ldcg(&g_v[k]);
            }
#pragma unroll
            for (int o = 16; o; o >>= 1) p += __shfl_xor_sync(0xffffffffu, p, o);
            if (lane == 0) g_uraw[r] = p;
        }
        global_barrier(c, ++bt);
        {   // normalize u / sigma
            float p = 0.f;
            for (int i = tid; i < DIM; i += NTHR) { float x = __ldcg(&g_uraw[i]); p += x*x; }
            nrm[tid] = p; __syncthreads();
            for (int o = 128; o > 0; o >>= 1) {
                if (tid < o) nrm[tid] += nrm[tid + o];
                __syncthreads();
            }
            float s2 = nrm[0];
            __syncthreads();
            if (it < 2) {
                float inv = 1.f / (sqrtf(s2) + EPSF);
                if (tid < 8) g_u[8*c + tid] = __ldcg(&g_uraw[8*c + tid]) * inv;
                global_barrier(c, ++bt);
            } else {
                sigma = s2 / (sqrtf(s2) + EPSF);   // |u . Wh v|
            }
        }
    }
    // all flags now equal bt for every CTA; counters equal bt2

    // ---- (c) W_eff slice into registers, pre-packed as f32x2 pairs ----
    unsigned long long w01[4][8], w23[4][8];
#pragma unroll
    for (int oi = 0; oi < 4; ++oi) {
        int d = dg*32 + 4*w + oi;
        float lr   = __ldg(&logr[d]);
        float rad  = MAXR / (1.f + expf(-lr));
        float mult = rad / (sigma + EPSF);
        const float* row = Wh + (size_t)d*DIM + 4*lane;
#pragma unroll
        for (int j = 0; j < 8; ++j) {
            float4 wv = *(const float4*)(row + 128*j);
            w01[oi][j] = pack2(wv.x*mult, wv.y*mult);
            w23[oi][j] = pack2(wv.z*mult, wv.w*mult);
        }
    }

    // epilogue mapping (lanes 0..15): bi = lane>>2, oi = lane&3
    const int eb   = 4*g + (lane >> 2);
    const int ed   = dg*32 + 4*w + (lane & 3);
    const int eidx = eb*DIM + ed;
    float* myred = red + w*576;
    unsigned* mycnts = &g_cnt[g*32];

    // ---- (d) recurrence : per-warp release publication --------------------
    const float* hsrc[2] = { &g_hbuf[0][4*g*DIM], &g_hbuf[1][4*g*DIM] };
    for (int t = 0; t < T_STEPS; ++t) {
        // prefetch G and z early (independent of h)
        float gpre = 0.f, zpre = 0.f;
        size_t gi = (size_t)t*BD + eidx;
        if (lane < 16) {
            gpre = __ldg(&g_G[gi]);
            zpre = __ldg(&z[gi]);
        }

        // WAIT: all 8 warps of all 32 group CTAs published step t-1
        if (tid < 32) {
            unsigned ok, tgt = bt2 + 8u*(unsigned)t;
            do { ok = (unsigned)(ld_acq(&mycnts[lane]) >= tgt); }
            while (!__all_sync(0xffffffffu, ok));
        }
        __syncthreads();

        // stage h via cp.async, split by k-half for overlap
        const float* src = hsrc[t & 1];
#pragma unroll
        for (int i = 0; i < 2; ++i) {
            int idx = i*NTHR + tid;               // 0..511
            int bi = idx >> 7, kl = idx & 127;    // k < 512
            int off = bi*1024 + kl*4;
            cp_async16(&h_sm[off], src + off);
        }
        cp_commit();
#pragma unroll
        for (int i = 0; i < 2; ++i) {
            int idx = i*NTHR + tid;
            int bi = idx >> 7, kl = idx & 127;    // k >= 512
            int off = bi*1024 + 512 + kl*4;
            cp_async16(&h_sm[off], src + off);
        }
        cp_commit();

        unsigned long long acc[4][4];
#pragma unroll
        for (int bi = 0; bi < 4; ++bi)
#pragma unroll
            for (int oi = 0; oi < 4; ++oi) acc[bi][oi] = 0ull;

        cp_wait1();
        __syncthreads();
#pragma unroll
        for (int j = 0; j < 4; ++j) {
#pragma unroll
            for (int bi = 0; bi < 4; ++bi) {
                unsigned long long h01, h23;
                asm volatile("ld.shared.v2.b64 {%0, %1}, [%2];"
                             : "=l"(h01), "=l"(h23)
                             : "r"(hbase + bi*4096 + j*512));
#pragma unroll
                for (int oi = 0; oi < 4; ++oi) {
                    fma2(acc[bi][oi], w01[oi][j], h01);
                    fma2(acc[bi][oi], w23[oi][j], h23);
                }
            }
        }
        cp_wait0();
        __syncthreads();
#pragma unroll
        for (int j = 4; j < 8; ++j) {
#pragma unroll
            for (int bi = 0; bi < 4; ++bi) {
                unsigned long long h01, h23;
                asm volatile("ld.shared.v2.b64 {%0, %1}, [%2];"
                             : "=l"(h01), "=l"(h23)
                             : "r"(hbase + bi*4096 + j*512));
#pragma unroll
                for (int oi = 0; oi < 4; ++oi) {
                    fma2(acc[bi][oi], w01[oi][j], h01);
                    fma2(acc[bi][oi], w23[oi][j], h23);
                }
            }
        }

        // fold f32x2 halves, reduce k across 32 lanes via padded smem
#pragma unroll
        for (int bi = 0; bi < 4; ++bi)
#pragma unroll
            for (int oi = 0; oi < 4; ++oi)
                myred[(bi*4 + oi)*36 + lane] = fold2(acc[bi][oi]);
        __syncwarp();

        float hn = 0.f, zv = 0.f;
        if (lane < 16) {
            const float* rr = myred + lane*36;
            float4 s4 = make_float4(0.f, 0.f, 0.f, 0.f);
#pragma unroll
            for (int q = 0; q < 8; ++q) {
                float4 v = *(const float4*)(rr + q*4);
                s4.x += v.x; s4.y += v.y; s4.z += v.z; s4.w += v.w;
            }
            float s = (s4.x + s4.y) + (s4.z + s4.w);
            hn = fast_tanh(s + gpre);
            zv = zpre;
            // CRITICAL-PATH store: next-step hidden state
            __stcg(&g_hbuf[(t + 1) & 1][eidx], hn);
        }
        // per-warp publish: syncwarp orders all 16 h stores before the release
        __syncwarp();
        if (lane == 0) red_rel_add1(&g_cnt[c]);

        // off-critical-path stores: gated output + h_all
        if (lane < 16) {
            float ov = hn * (zv / (1.f + __expf(-zv)));   // h * silu(z)
            outs[gi]       = ov;
            h_all[gi + BD] = hn;
        }
    }
}

// ---------------- launch -----------------------------------------------------
extern "C" void kernel_launch(void* const* d_in, const int* in_sizes, int n_in,
                              void* d_out, int out_size) {
    const float* x    = (const float*)d_in[0];
    const float* z    = (const float*)d_in[1];
    const float* h0   = (const float*)d_in[2];
    const float* Wx   = (const float*)d_in[3];
    const float* Wh   = (const float*)d_in[4];
    const float* logr = (const float*)d_in[5];
    const float* b    = (const float*)d_in[6];
    const float* u0   = (const float*)d_in[7];
    float* out = (float*)d_out;

    gemm_kernel<<<dim3(DIM/128, (T_STEPS*BATCH)/128), 256>>>(x, Wx, b);
    rnn_kernel<<<NCTA, NTHR>>>(z, h0, Wh, logr, u0, out);
}